// round 15
// baseline (speedup 1.0000x reference)
#include <cuda_runtime.h>
#include <cuda_fp16.h>
#include <cstdint>
#include <math.h>

#define NN 524288
#define EE 4194304
#define BB 16384
#define SLOPE 0.2f

// ---------------- scratch (device globals; no allocation allowed) ----------------
__device__ int   d_rowptr[NN + 1];
__device__ int   d_cursor[NN];
__device__ int   d_bsum[512];
__device__ int   d_col[EE + NN];
__device__ float d_hbuf[NN * 32];
__device__ float d_gbuf[NN * 32];
__device__ float d_sv[NN];
__device__ float d_tvv[NN];
__device__ float d_c1[BB * 100];
__device__ float d_scl[1300];
__device__ float d_shf[1300];

// fp16 buffers: activations hi-only; weights hi(+lo where used). K %32==0, rows padded to 64.
constexpr long O_AFP  = 0;                          // fp input [16384 x 1024]
constexpr long O_ATV  = O_AFP + 16384L * 1024;      // tv input [16384 x 256]
constexpr long O_FP1  = O_ATV + 16384L * 256;       // fc1 out [16384 x 448] (400 valid)
constexpr long O_TV1  = O_FP1 + 16384L * 448;       // fc3 out [16384 x 448]
constexpr long O_CMB  = O_TV1 + 16384L * 448;       // comb [16384 x 448]
constexpr long O_W1_H = O_CMB + 16384L * 448;       // w1t [448 x 1024] (400 valid rows)
constexpr long O_W1_L = O_W1_H + 448L * 1024;       // (unused)
constexpr long O_W2_H = O_W1_L + 448L * 1024;       // w2t [256 x 448] (200 valid)
constexpr long O_W2_L = O_W2_H + 256L * 448;
constexpr long O_W3_H = O_W2_L + 256L * 448;        // w3t [448 x 256] (400 valid)
constexpr long O_W3_L = O_W3_H + 448L * 256;        // (unused)
constexpr long O_W4_H = O_W3_L + 448L * 256;        // w4t [256 x 448] (200 valid)
constexpr long O_W4_L = O_W4_H + 256L * 448;
constexpr long O_WC_H = O_W4_L + 256L * 448;        // wct [128 x 448] (100 valid)
constexpr long O_WC_L = O_WC_H + 128L * 448;
constexpr long O_END  = O_WC_L + 128L * 448;
__device__ __half g_hf[O_END];

// ---------------- CSR build ----------------
__global__ void k_init_deg() {
    int i = blockIdx.x * blockDim.x + threadIdx.x;
    if (i < NN) d_cursor[i] = 1;
}

__global__ void k_count(const int* __restrict__ ei, int E) {
    int e = blockIdx.x * blockDim.x + threadIdx.x;
    if (e >= E) return;
    atomicAdd(&d_cursor[ei[E + e]], 1);
}

__global__ void k_blocksum() {
    __shared__ int s[1024];
    int i = blockIdx.x * 1024 + threadIdx.x;
    s[threadIdx.x] = d_cursor[i];
    __syncthreads();
    for (int o = 512; o > 0; o >>= 1) {
        if (threadIdx.x < o) s[threadIdx.x] += s[threadIdx.x + o];
        __syncthreads();
    }
    if (threadIdx.x == 0) d_bsum[blockIdx.x] = s[0];
}

__global__ void k_scan_bsums() {
    __shared__ int s[512];
    int tid = threadIdx.x;
    int v = d_bsum[tid];
    s[tid] = v;
    __syncthreads();
    for (int o = 1; o < 512; o <<= 1) {
        int t = (tid >= o) ? s[tid - o] : 0;
        __syncthreads();
        s[tid] += t;
        __syncthreads();
    }
    d_bsum[tid] = s[tid] - v;
}

__global__ void k_scan_final() {
    __shared__ int s[1024];
    int tid = threadIdx.x;
    int i = blockIdx.x * 1024 + tid;
    int v = d_cursor[i];
    s[tid] = v;
    __syncthreads();
    for (int o = 1; o < 1024; o <<= 1) {
        int t = (tid >= o) ? s[tid - o] : 0;
        __syncthreads();
        s[tid] += t;
        __syncthreads();
    }
    int ex = s[tid] - v + d_bsum[blockIdx.x];
    d_rowptr[i] = ex;
    d_cursor[i] = ex;
    if (i == NN - 1) d_rowptr[NN] = ex + v;
}

__global__ void k_fill(const int* __restrict__ ei, int E) {
    int e = blockIdx.x * blockDim.x + threadIdx.x;
    if (e >= E + NN) return;
    int src, dst;
    if (e < E) { src = ei[e]; dst = ei[E + e]; }
    else       { src = dst = e - E; }
    int pos = atomicAdd(&d_cursor[dst], 1);
    d_col[pos] = src;
}

// ---------------- node-wise linear (fp32 H) ----------------
template <int CIN, int CINS, int COUT, int COUTS>
__global__ void k_node_linear(const float* __restrict__ X, const float* __restrict__ W,
                              const float* __restrict__ asrc, const float* __restrict__ adst,
                              float* __restrict__ H, float* __restrict__ S, float* __restrict__ T) {
    __shared__ float sW[CIN * COUT];
    __shared__ float sa[COUT], sd[COUT];
    for (int i = threadIdx.x; i < CIN * COUT; i += blockDim.x) sW[i] = W[i];
    for (int i = threadIdx.x; i < COUT; i += blockDim.x) { sa[i] = asrc[i]; sd[i] = adst[i]; }
    __syncthreads();
    int i = blockIdx.x * blockDim.x + threadIdx.x;
    if (i >= NN) return;
    float xr[CIN];
#pragma unroll
    for (int k = 0; k < CIN; k++) xr[k] = X[(long)i * CINS + k];
    float acc[COUT];
#pragma unroll
    for (int j = 0; j < COUT; j++) acc[j] = 0.f;
#pragma unroll
    for (int k = 0; k < CIN; k++) {
        float xv = xr[k];
#pragma unroll
        for (int j = 0; j < COUT; j++) acc[j] = fmaf(xv, sW[k * COUT + j], acc[j]);
    }
    float s = 0.f, t = 0.f;
#pragma unroll
    for (int j = 0; j < COUT; j++) { s = fmaf(acc[j], sa[j], s); t = fmaf(acc[j], sd[j], t); }
#pragma unroll
    for (int j = 0; j < COUTS; j++)
        H[(long)i * COUTS + j] = (j < COUT) ? acc[j] : 0.f;
    S[i] = s;
    T[i] = t;
}

// ---------------- GAT aggregation: chunk-8 batched loads + chunked online softmax ----------------
template <int C, int HS, int OUTS>
__global__ void k_gat_agg(const float* __restrict__ H, const float* __restrict__ S,
                          const float* __restrict__ T, const float* __restrict__ bias,
                          float* __restrict__ OUT) {
    int warp = (blockIdx.x * blockDim.x + threadIdx.x) >> 5;
    int lane = threadIdx.x & 31;
    if (warp >= NN) return;
    int p0 = d_rowptr[warp];
    int p1 = d_rowptr[warp + 1];
    float ti = T[warp];
    bool fl = (lane < C);
    float m = -INFINITY, sum = 0.f, acc = 0.f;
    for (int p = p0; p < p1; p += 8) {
        int n = p1 - p;
        int sidx[8];
        float ee[8], hh[8];
#pragma unroll
        for (int j = 0; j < 8; j++) sidx[j] = (j < n) ? __ldg(&d_col[p + j]) : 0;
#pragma unroll
        for (int j = 0; j < 8; j++) ee[j] = (j < n) ? S[sidx[j]] + ti : -INFINITY;
#pragma unroll
        for (int j = 0; j < 8; j++) hh[j] = (fl && j < n) ? H[(long)sidx[j] * HS + lane] : 0.f;
#pragma unroll
        for (int j = 0; j < 8; j++) ee[j] = (ee[j] > 0.f) ? ee[j] : SLOPE * ee[j];
        float cm = fmaxf(fmaxf(fmaxf(ee[0], ee[1]), fmaxf(ee[2], ee[3])),
                         fmaxf(fmaxf(ee[4], ee[5]), fmaxf(ee[6], ee[7])));
        if (cm > m) {
            float sc = __expf(m - cm);   // first chunk: exp(-inf)=0
            sum *= sc;
            acc *= sc;
            m = cm;
        }
#pragma unroll
        for (int j = 0; j < 8; j++) {
            float w = __expf(ee[j] - m);
            sum += w;
            acc = fmaf(w, hh[j], acc);
        }
    }
    if (fl) {
        float v = acc / sum + bias[lane];
        OUT[(long)warp * OUTS + lane] = (v > 0.f) ? v : 0.f;
    } else if (lane < OUTS) {
        OUT[(long)warp * OUTS + lane] = 0.f;
    }
}

// ---------------- pool: warp per graph -> comb fp16 ----------------
__global__ void k_pool(const int* __restrict__ batch, const float* __restrict__ G,
                       __half* __restrict__ ch) {
    int warp = (blockIdx.x * blockDim.x + threadIdx.x) >> 5;
    int lane = threadIdx.x & 31;
    if (warp >= BB) return;
    int b = warp;
    int lo = 0, hi = NN;
    while (lo < hi) { int mid = (lo + hi) >> 1; if (batch[mid] < b) lo = mid + 1; else hi = mid; }
    int start = lo;
    hi = NN;
    while (lo < hi) { int mid = (lo + hi) >> 1; if (batch[mid] < b + 1) lo = mid + 1; else hi = mid; }
    int end = lo;
    float s = 0.f;
    for (int r = start; r < end; r++) s += G[(long)r * 32 + lane];
    ch[(long)b * 448 + lane] = __float2half(s);
}

// ---------------- BN/bias fold ----------------
__global__ void k_prep(const float* __restrict__ bias, const float* __restrict__ bn, int n,
                       float* __restrict__ sc, float* __restrict__ sh) {
    int j = blockIdx.x * blockDim.x + threadIdx.x;
    if (j >= n) return;
    float g = bn[j], be = bn[n + j], mu = bn[2 * n + j], va = bn[3 * n + j];
    float s = g * rsqrtf(va + 1e-5f);
    sc[j] = s;
    sh[j] = (bias[j] - mu) * s + be;
}

// ---------------- activation fp32 -> fp16 (hi only, x4 vectorized) ----------------
__global__ void k_ahalf(const float* __restrict__ in, __half* __restrict__ h, long n4) {
    long i = (long)blockIdx.x * blockDim.x + threadIdx.x;
    if (i >= n4) return;
    float4 v = *reinterpret_cast<const float4*>(in + i * 4);
    __half2* hp = reinterpret_cast<__half2*>(h + i * 4);
    hp[0] = __floats2half2_rn(v.x, v.y);
    hp[1] = __floats2half2_rn(v.z, v.w);
}

// weight [K][N] -> transposed fp16 hi(+lo) split, padded to [Np][Kp]; tl may be null
__global__ void k_whalf(const float* __restrict__ w, int K, int N, int Kp, int Np,
                        __half* __restrict__ th, __half* __restrict__ tl) {
    long i = (long)blockIdx.x * blockDim.x + threadIdx.x;
    if (i >= (long)Np * Kp) return;
    int n = (int)(i / Kp);
    int k = (int)(i % Kp);
    float v = (k < K && n < N) ? w[(long)k * N + n] : 0.f;
    __half hv = __float2half(v);
    th[i] = hv;
    if (tl) tl[i] = __float2half(v - __half2float(hv));
}

// ---------------- tensor-core GEMM (fp16; templated 1/2-MMA, cp.async 2-stage) ----------------
#define LDSM4(r0, r1, r2, r3, addr) \
    asm volatile("ldmatrix.sync.aligned.m8n8.x4.shared.b16 {%0,%1,%2,%3}, [%4];" \
                 : "=r"(r0), "=r"(r1), "=r"(r2), "=r"(r3) : "r"(addr))

#define MMA16816(c, a, b) \
    asm volatile("mma.sync.aligned.m16n8k16.row.col.f32.f16.f16.f32 " \
                 "{%0,%1,%2,%3}, {%4,%5,%6,%7}, {%8,%9}, {%0,%1,%2,%3};" \
                 : "+f"(c[0]), "+f"(c[1]), "+f"(c[2]), "+f"(c[3]) \
                 : "r"(a[0]), "r"(a[1]), "r"(a[2]), "r"(a[3]), "r"(b[0]), "r"(b[1]))

#define CPA16(d, s) asm volatile("cp.async.cg.shared.global [%0], [%1], 16;" :: "r"(d), "l"(s))
#define CP_COMMIT   asm volatile("cp.async.commit_group;")
#define CP_WAIT1    asm volatile("cp.async.wait_group 1;")
#define CP_WAIT0    asm volatile("cp.async.wait_group 0;")

// smem halves-stride 40 (80B rows): conflict-free 8-row ldmatrix.
#define SAW 40
#define SM_STG   20480
#define SM_BH    10240
#define SM_BL    15360
#define SM_TOTAL 40960

// C = relu((A @ (Bh[+Bl])^T) * sc + sh). A [16384 x Kp] fp16; B [Np x Kp] fp16.
template <bool USEL>
__global__ __launch_bounds__(256) void k_mma(
    const __half* __restrict__ Ah,
    const __half* __restrict__ Bh, const __half* __restrict__ Bl,
    int Kp,
    const float* __restrict__ sc, const float* __restrict__ sh,
    float* __restrict__ outF, __half* __restrict__ outH,
    int ldc, int cofs, int Nstore, int Nzero) {
    extern __shared__ __align__(128) __half dsm[];
    uint32_t sb = (uint32_t)__cvta_generic_to_shared(dsm);
    int tid = threadIdx.x;
    int lane = tid & 31, warp = tid >> 5;
    int wm = warp >> 1, wn = warp & 1;
    int bm = blockIdx.y * 128, bn = blockIdx.x * 64;

    float acc[2][4][4];
#pragma unroll
    for (int mi = 0; mi < 2; mi++)
#pragma unroll
        for (int ni = 0; ni < 4; ni++)
#pragma unroll
            for (int r = 0; r < 4; r++) acc[mi][ni][r] = 0.f;

    int ar = tid >> 2;           // 0..63
    int ac = (tid & 3) * 8;      // 0,8,16,24

    auto issue = [&](int kt, int stg) {
        long k0 = (long)kt * 32 + ac;
        uint32_t base = sb + stg * SM_STG;
#pragma unroll
        for (int rr = 0; rr < 2; rr++) {
            int row = ar + rr * 64;
            CPA16(base + ((row * SAW + ac) << 1), Ah + (long)(bm + row) * Kp + k0);
        }
        CPA16(base + SM_BH + ((ar * SAW + ac) << 1), Bh + (long)(bn + ar) * Kp + k0);
        if (USEL)
            CPA16(base + SM_BL + ((ar * SAW + ac) << 1), Bl + (long)(bn + ar) * Kp + k0);
    };

    int T = Kp >> 5;
    issue(0, 0);
    CP_COMMIT;
    int stg = 0;
    for (int kt = 0; kt < T; kt++) {
        if (kt + 1 < T) {
            issue(kt + 1, stg ^ 1);
            CP_COMMIT;
            CP_WAIT1;
        } else {
            CP_WAIT0;
        }
        __syncthreads();
        uint32_t base = sb + stg * SM_STG;
#pragma unroll
        for (int ks = 0; ks < 2; ks++) {
            uint32_t a_[2][4], bh_[4][2];
#pragma unroll
            for (int mi = 0; mi < 2; mi++) {
                int row = wm * 32 + mi * 16 + (lane & 15);
                int col = ks * 16 + (lane >> 4) * 8;
                uint32_t ad = base + ((row * SAW + col) << 1);
                LDSM4(a_[mi][0], a_[mi][1], a_[mi][2], a_[mi][3], ad);
            }
#pragma unroll
            for (int nh = 0; nh < 2; nh++) {
                int p = lane >> 3, l7 = lane & 7;
                int nrow = wn * 32 + nh * 16 + (p >> 1) * 8 + l7;
                int col = ks * 16 + (p & 1) * 8;
                uint32_t ad = base + SM_BH + ((nrow * SAW + col) << 1);
                LDSM4(bh_[2 * nh][0], bh_[2 * nh][1], bh_[2 * nh + 1][0], bh_[2 * nh + 1][1], ad);
            }
#pragma unroll
            for (int mi = 0; mi < 2; mi++)
#pragma unroll
                for (int ni = 0; ni < 4; ni++)
                    MMA16816(acc[mi][ni], a_[mi], bh_[ni]);
            if (USEL) {
                uint32_t bl_[4][2];
#pragma unroll
                for (int nh = 0; nh < 2; nh++) {
                    int p = lane >> 3, l7 = lane & 7;
                    int nrow = wn * 32 + nh * 16 + (p >> 1) * 8 + l7;
                    int col = ks * 16 + (p & 1) * 8;
                    uint32_t ad = base + SM_BL + ((nrow * SAW + col) << 1);
                    LDSM4(bl_[2 * nh][0], bl_[2 * nh][1], bl_[2 * nh + 1][0], bl_[2 * nh + 1][1], ad);
                }
#pragma unroll
                for (int mi = 0; mi < 2; mi++)
#pragma unroll
                    for (int ni = 0; ni < 4; ni++)
                        MMA16816(acc[mi][ni], a_[mi], bl_[ni]);
            }
        }
        __syncthreads();
        stg ^= 1;
    }

    // epilogue: scale/shift + relu, write fp32 or fp16
    int g = lane >> 2, t2 = (lane & 3) * 2;
#pragma unroll
    for (int mi = 0; mi < 2; mi++)
#pragma unroll
        for (int ni = 0; ni < 4; ni++)
#pragma unroll
            for (int r = 0; r < 4; r++) {
                int gm = bm + wm * 32 + mi * 16 + g + ((r >> 1) * 8);
                int gn = bn + wn * 32 + ni * 8 + t2 + (r & 1);
                if (gn < Nzero) {
                    float val = 0.f;
                    if (gn < Nstore) {
                        val = acc[mi][ni][r] * sc[gn] + sh[gn];
                        val = (val > 0.f) ? val : 0.f;
                    }
                    long o = (long)gm * ldc + cofs + gn;
                    if (outF) outF[o] = val;
                    else      outH[o] = __float2half(val);
                }
            }
}

// ---------------- final fc ----------------
__global__ void k_final(const float* __restrict__ Cc, const float* __restrict__ w,
                        const float* __restrict__ b, float* __restrict__ out) {
    int m = blockIdx.x * blockDim.x + threadIdx.x;
    if (m >= BB) return;
    float s = b[0];
#pragma unroll 4
    for (int j = 0; j < 100; j++) s = fmaf(Cc[(long)m * 100 + j], w[j], s);
    out[m] = s;
}

// ---------------- launch ----------------
extern "C" void kernel_launch(void* const* d_in, const int* in_sizes, int n_in,
                              void* d_out, int out_size) {
    const float* x      = (const float*)d_in[0];
    const int*   ei     = (const int*)d_in[1];
    const int*   batch  = (const int*)d_in[2];
    const float* fp     = (const float*)d_in[3];
    const float* tvf    = (const float*)d_in[4];
    const float* W1     = (const float*)d_in[5];
    const float* as1    = (const float*)d_in[6];
    const float* ad1    = (const float*)d_in[7];
    const float* b1     = (const float*)d_in[8];
    const float* W2     = (const float*)d_in[9];
    const float* as2    = (const float*)d_in[10];
    const float* ad2    = (const float*)d_in[11];
    const float* b2     = (const float*)d_in[12];
    const float* fc1_w  = (const float*)d_in[13];
    const float* fc1_b  = (const float*)d_in[14];
    const float* bn1    = (const float*)d_in[15];
    const float* fc2_w  = (const float*)d_in[16];
    const float* fc2_b  = (const float*)d_in[17];
    const float* bn2    = (const float*)d_in[18];
    const float* fc3_w  = (const float*)d_in[19];
    const float* fc3_b  = (const float*)d_in[20];
    const float* bn3    = (const float*)d_in[21];
    const float* fc4_w  = (const float*)d_in[22];
    const float* fc4_b  = (const float*)d_in[23];
    const float* bn4    = (const float*)d_in[24];
    const float* fcc1_w = (const float*)d_in[25];
    const float* fcc1_b = (const float*)d_in[26];
    const float* bnc    = (const float*)d_in[27];
    const float* fcc2_w = (const float*)d_in[28];
    const float* fcc2_b = (const float*)d_in[29];
    float* out = (float*)d_out;

    int E = in_sizes[1] / 2;

    static int inited = 0;
    static cudaStream_t sB = 0;
    static cudaEvent_t evF = 0, evJ = 0;
    if (!inited) {
        cudaFuncSetAttribute(k_mma<true>, cudaFuncAttributeMaxDynamicSharedMemorySize, SM_TOTAL);
        cudaFuncSetAttribute(k_mma<false>, cudaFuncAttributeMaxDynamicSharedMemorySize, SM_TOTAL);
        cudaStreamCreateWithFlags(&sB, cudaStreamNonBlocking);
        cudaEventCreateWithFlags(&evF, cudaEventDisableTiming);
        cudaEventCreateWithFlags(&evJ, cudaEventDisableTiming);
        inited = 1;
    }

    void *p_h, *p_g, *p_s, *p_t, *p_c1, *p_sc, *p_sh, *p_hf;
    cudaGetSymbolAddress(&p_h, d_hbuf);
    cudaGetSymbolAddress(&p_g, d_gbuf);
    cudaGetSymbolAddress(&p_s, d_sv);
    cudaGetSymbolAddress(&p_t, d_tvv);
    cudaGetSymbolAddress(&p_c1, d_c1);
    cudaGetSymbolAddress(&p_sc, d_scl);
    cudaGetSymbolAddress(&p_sh, d_shf);
    cudaGetSymbolAddress(&p_hf, g_hf);
    float* hbuf = (float*)p_h;  float* gbuf = (float*)p_g;
    float* sv = (float*)p_s;    float* tv = (float*)p_t;
    float* c1 = (float*)p_c1;
    float* scl = (float*)p_sc;  float* shf = (float*)p_sh;
    __half* hf = (__half*)p_hf;

    // fork: graph branch on sB, dense branch on stream 0
    cudaEventRecord(evF, 0);
    cudaStreamWaitEvent(sB, evF, 0);

    // ---- dense branch prologue (stream 0) ----
    {
        long n4 = 16384L * 1024 / 4;
        k_ahalf<<<(int)((n4 + 255) / 256), 256>>>(fp, hf + O_AFP, n4);
    }
    k_whalf<<<(448 * 1024 + 255) / 256, 256>>>(fc1_w, 1024, 400, 1024, 448, hf + O_W1_H, nullptr);
    k_prep<<<2, 256>>>(fc1_b, bn1, 400, scl + 0, shf + 0);
    {
        long n4 = 16384L * 256 / 4;
        k_ahalf<<<(int)((n4 + 255) / 256), 256>>>(tvf, hf + O_ATV, n4);
    }
    k_whalf<<<(448 * 256 + 255) / 256, 256>>>(fc3_w, 256, 400, 256, 448, hf + O_W3_H, nullptr);
    // fc1: [16384,1024]x[1024,400] -> fp1 [16384 x 448]  (1-MMA)
    k_mma<false><<<dim3(7, 128), 256, SM_TOTAL>>>(hf + O_AFP, hf + O_W1_H, nullptr,
                                                  1024, scl + 0, shf + 0,
                                                  nullptr, hf + O_FP1, 448, 0, 400, 448);

    // ---- graph branch (stream sB): CSR + GAT x2 + pool ----
    k_init_deg<<<(NN + 255) / 256, 256, 0, sB>>>();
    k_count<<<(E + 255) / 256, 256, 0, sB>>>(ei, E);
    k_blocksum<<<512, 1024, 0, sB>>>();
    k_scan_bsums<<<1, 512, 0, sB>>>();
    k_scan_final<<<512, 1024, 0, sB>>>();
    k_fill<<<(E + NN + 255) / 256, 256, 0, sB>>>(ei, E);
    k_node_linear<14, 14, 14, 16><<<(NN + 255) / 256, 256, 0, sB>>>(x, W1, as1, ad1, hbuf, sv, tv);
    k_gat_agg<14, 16, 16><<<(NN * 32 + 255) / 256, 256, 0, sB>>>(hbuf, sv, tv, b1, gbuf);
    k_node_linear<14, 16, 32, 32><<<(NN + 255) / 256, 256, 0, sB>>>(gbuf, W2, as2, ad2, hbuf, sv, tv);
    k_gat_agg<32, 32, 32><<<(NN * 32 + 255) / 256, 256, 0, sB>>>(hbuf, sv, tv, b2, gbuf);
    k_pool<<<(BB * 32 + 255) / 256, 256, 0, sB>>>(batch, gbuf, hf + O_CMB);

    // ---- dense branch continues (stream 0) ----
    k_prep<<<2, 256>>>(fc3_b, bn3, 400, scl + 600, shf + 600);
    // fc3: [16384,256]x[256,400] -> tv1  (1-MMA)
    k_mma<false><<<dim3(7, 128), 256, SM_TOTAL>>>(hf + O_ATV, hf + O_W3_H, nullptr,
                                                  256, scl + 600, shf + 600,
                                                  nullptr, hf + O_TV1, 448, 0, 400, 448);
    k_whalf<<<(256 * 448 + 255) / 256, 256>>>(fc2_w, 400, 200, 448, 256, hf + O_W2_H, hf + O_W2_L);
    k_prep<<<1, 256>>>(fc2_b, bn2, 200, scl + 400, shf + 400);
    // fc2: [16384,448]x[448,200] -> comb[:,32:232]  (2-MMA)
    k_mma<true><<<dim3(4, 128), 256, SM_TOTAL>>>(hf + O_FP1, hf + O_W2_H, hf + O_W2_L,
                                                 448, scl + 400, shf + 400,
                                                 nullptr, hf + O_CMB, 448, 32, 200, 200);
    k_whalf<<<(256 * 448 + 255) / 256, 256>>>(fc4_w, 400, 200, 448, 256, hf + O_W4_H, hf + O_W4_L);
    k_prep<<<1, 256>>>(fc4_b, bn4, 200, scl + 1000, shf + 1000);
    // fc4: [16384,448]x[448,200] -> comb[:,232:432], zero comb[:,432:448]  (2-MMA)
    k_mma<true><<<dim3(4, 128), 256, SM_TOTAL>>>(hf + O_TV1, hf + O_W4_H, hf + O_W4_L,
                                                 448, scl + 1000, shf + 1000,
                                                 nullptr, hf + O_CMB, 448, 232, 200, 216);
    k_whalf<<<(128 * 448 + 255) / 256, 256>>>(fcc1_w, 432, 100, 448, 128, hf + O_WC_H, hf + O_WC_L);
    k_prep<<<1, 128>>>(fcc1_b, bnc, 100, scl + 1200, shf + 1200);

    // join: fcc1 needs comb (pool on sB + fc2/fc4 on 0)
    cudaEventRecord(evJ, sB);
    cudaStreamWaitEvent(0, evJ, 0);

    // fcc1: [16384,448]x[448,100] -> c1 fp32  (2-MMA)
    k_mma<true><<<dim3(2, 128), 256, SM_TOTAL>>>(hf + O_CMB, hf + O_WC_H, hf + O_WC_L,
                                                 448, scl + 1200, shf + 1200,
                                                 c1, nullptr, 100, 0, 100, 100);
    k_final<<<(BB + 127) / 128, 128>>>(c1, fcc2_w, fcc2_b, out);
}

// round 17
// speedup vs baseline: 1.9230x; 1.9230x over previous
#include <cuda_runtime.h>
#include <cuda_fp16.h>
#include <cstdint>
#include <math.h>

#define NN 524288
#define EE 4194304
#define BB 16384
#define SLOPE 0.2f

// ---------------- scratch (device globals; no allocation allowed) ----------------
__device__ int   d_rowptr[NN + 1];
__device__ int   d_cursor[NN];
__device__ int   d_bsum[512];
__device__ int   d_col[EE + NN];
__device__ float d_hbuf[NN * 32];
__device__ float d_gbuf[NN * 32];
__device__ float d_sv[NN];
__device__ float d_tvv[NN];
__device__ float d_c1[BB * 100];
__device__ float d_scl[1300];
__device__ float d_shf[1300];

// fp16 buffers: activations hi-only; weights hi(+lo where used). K %32==0, rows padded to 64.
constexpr long O_AFP  = 0;                          // fp input [16384 x 1024]
constexpr long O_ATV  = O_AFP + 16384L * 1024;      // tv input [16384 x 256]
constexpr long O_FP1  = O_ATV + 16384L * 256;       // fc1 out [16384 x 448] (400 valid)
constexpr long O_TV1  = O_FP1 + 16384L * 448;       // fc3 out [16384 x 448]
constexpr long O_CMB  = O_TV1 + 16384L * 448;       // comb [16384 x 448]
constexpr long O_W1_H = O_CMB + 16384L * 448;       // w1t [448 x 1024] (400 valid rows)
constexpr long O_W1_L = O_W1_H + 448L * 1024;       // (unused)
constexpr long O_W2_H = O_W1_L + 448L * 1024;       // w2t [256 x 448] (200 valid)
constexpr long O_W2_L = O_W2_H + 256L * 448;
constexpr long O_W3_H = O_W2_L + 256L * 448;        // w3t [448 x 256] (400 valid)
constexpr long O_W3_L = O_W3_H + 448L * 256;        // (unused)
constexpr long O_W4_H = O_W3_L + 448L * 256;        // w4t [256 x 448] (200 valid)
constexpr long O_W4_L = O_W4_H + 256L * 448;
constexpr long O_WC_H = O_W4_L + 256L * 448;        // wct [128 x 448] (100 valid)
constexpr long O_WC_L = O_WC_H + 128L * 448;
constexpr long O_END  = O_WC_L + 128L * 448;
__device__ __half g_hf[O_END];

// ---------------- CSR build ----------------
__global__ void k_init_deg() {
    int i = blockIdx.x * blockDim.x + threadIdx.x;
    if (i < NN) d_cursor[i] = 1;
}

__global__ void k_count(const int* __restrict__ ei, int E) {
    int e = blockIdx.x * blockDim.x + threadIdx.x;
    if (e >= E) return;
    atomicAdd(&d_cursor[ei[E + e]], 1);
}

__global__ void k_blocksum() {
    __shared__ int s[1024];
    int i = blockIdx.x * 1024 + threadIdx.x;
    s[threadIdx.x] = d_cursor[i];
    __syncthreads();
    for (int o = 512; o > 0; o >>= 1) {
        if (threadIdx.x < o) s[threadIdx.x] += s[threadIdx.x + o];
        __syncthreads();
    }
    if (threadIdx.x == 0) d_bsum[blockIdx.x] = s[0];
}

__global__ void k_scan_bsums() {
    __shared__ int s[512];
    int tid = threadIdx.x;
    int v = d_bsum[tid];
    s[tid] = v;
    __syncthreads();
    for (int o = 1; o < 512; o <<= 1) {
        int t = (tid >= o) ? s[tid - o] : 0;
        __syncthreads();
        s[tid] += t;
        __syncthreads();
    }
    d_bsum[tid] = s[tid] - v;
}

__global__ void k_scan_final() {
    __shared__ int s[1024];
    int tid = threadIdx.x;
    int i = blockIdx.x * 1024 + tid;
    int v = d_cursor[i];
    s[tid] = v;
    __syncthreads();
    for (int o = 1; o < 1024; o <<= 1) {
        int t = (tid >= o) ? s[tid - o] : 0;
        __syncthreads();
        s[tid] += t;
        __syncthreads();
    }
    int ex = s[tid] - v + d_bsum[blockIdx.x];
    d_rowptr[i] = ex;
    d_cursor[i] = ex;
    if (i == NN - 1) d_rowptr[NN] = ex + v;
}

__global__ void k_fill(const int* __restrict__ ei, int E) {
    int e = blockIdx.x * blockDim.x + threadIdx.x;
    if (e >= E + NN) return;
    int src, dst;
    if (e < E) { src = ei[e]; dst = ei[E + e]; }
    else       { src = dst = e - E; }
    int pos = atomicAdd(&d_cursor[dst], 1);
    d_col[pos] = src;
}

// ---------------- node-wise linear (fp32 H) ----------------
template <int CIN, int CINS, int COUT, int COUTS>
__global__ void k_node_linear(const float* __restrict__ X, const float* __restrict__ W,
                              const float* __restrict__ asrc, const float* __restrict__ adst,
                              float* __restrict__ H, float* __restrict__ S, float* __restrict__ T) {
    __shared__ float sW[CIN * COUT];
    __shared__ float sa[COUT], sd[COUT];
    for (int i = threadIdx.x; i < CIN * COUT; i += blockDim.x) sW[i] = W[i];
    for (int i = threadIdx.x; i < COUT; i += blockDim.x) { sa[i] = asrc[i]; sd[i] = adst[i]; }
    __syncthreads();
    int i = blockIdx.x * blockDim.x + threadIdx.x;
    if (i >= NN) return;
    float xr[CIN];
#pragma unroll
    for (int k = 0; k < CIN; k++) xr[k] = X[(long)i * CINS + k];
    float acc[COUT];
#pragma unroll
    for (int j = 0; j < COUT; j++) acc[j] = 0.f;
#pragma unroll
    for (int k = 0; k < CIN; k++) {
        float xv = xr[k];
#pragma unroll
        for (int j = 0; j < COUT; j++) acc[j] = fmaf(xv, sW[k * COUT + j], acc[j]);
    }
    float s = 0.f, t = 0.f;
#pragma unroll
    for (int j = 0; j < COUT; j++) { s = fmaf(acc[j], sa[j], s); t = fmaf(acc[j], sd[j], t); }
#pragma unroll
    for (int j = 0; j < COUTS; j++)
        H[(long)i * COUTS + j] = (j < COUT) ? acc[j] : 0.f;
    S[i] = s;
    T[i] = t;
}

// ---------------- GAT aggregation: chunk-4 batched loads + chunked online softmax ----------------
template <int C, int HS, int OUTS>
__global__ void k_gat_agg(const float* __restrict__ H, const float* __restrict__ S,
                          const float* __restrict__ T, const float* __restrict__ bias,
                          float* __restrict__ OUT) {
    int warp = (blockIdx.x * blockDim.x + threadIdx.x) >> 5;
    int lane = threadIdx.x & 31;
    if (warp >= NN) return;
    int p0 = d_rowptr[warp];
    int p1 = d_rowptr[warp + 1];
    float ti = T[warp];
    bool fl = (lane < C);
    float m = -INFINITY, sum = 0.f, acc = 0.f;
    for (int p = p0; p < p1; p += 4) {
        int n = p1 - p;
        int s0 = __ldg(&d_col[p]);
        int s1 = (n > 1) ? __ldg(&d_col[p + 1]) : 0;
        int s2 = (n > 2) ? __ldg(&d_col[p + 2]) : 0;
        int s3 = (n > 3) ? __ldg(&d_col[p + 3]) : 0;
        float e0 = S[s0] + ti;
        float e1 = (n > 1) ? S[s1] + ti : -INFINITY;
        float e2 = (n > 2) ? S[s2] + ti : -INFINITY;
        float e3 = (n > 3) ? S[s3] + ti : -INFINITY;
        float h0 = fl ? H[(long)s0 * HS + lane] : 0.f;
        float h1 = (fl && n > 1) ? H[(long)s1 * HS + lane] : 0.f;
        float h2 = (fl && n > 2) ? H[(long)s2 * HS + lane] : 0.f;
        float h3 = (fl && n > 3) ? H[(long)s3 * HS + lane] : 0.f;
        e0 = (e0 > 0.f) ? e0 : SLOPE * e0;
        e1 = (e1 > 0.f) ? e1 : SLOPE * e1;
        e2 = (e2 > 0.f) ? e2 : SLOPE * e2;
        e3 = (e3 > 0.f) ? e3 : SLOPE * e3;
        float cm = fmaxf(fmaxf(e0, e1), fmaxf(e2, e3));
        if (cm > m) {
            float sc = __expf(m - cm);
            sum *= sc;
            acc *= sc;
            m = cm;
        }
        float w0 = __expf(e0 - m);
        float w1 = __expf(e1 - m);
        float w2 = __expf(e2 - m);
        float w3 = __expf(e3 - m);
        sum += (w0 + w1) + (w2 + w3);
        acc = fmaf(w0, h0, acc);
        acc = fmaf(w1, h1, acc);
        acc = fmaf(w2, h2, acc);
        acc = fmaf(w3, h3, acc);
    }
    if (fl) {
        float v = acc / sum + bias[lane];
        OUT[(long)warp * OUTS + lane] = (v > 0.f) ? v : 0.f;
    } else if (lane < OUTS) {
        OUT[(long)warp * OUTS + lane] = 0.f;
    }
}

// ---------------- pool: warp per graph -> comb fp16 ----------------
__global__ void k_pool(const int* __restrict__ batch, const float* __restrict__ G,
                       __half* __restrict__ ch) {
    int warp = (blockIdx.x * blockDim.x + threadIdx.x) >> 5;
    int lane = threadIdx.x & 31;
    if (warp >= BB) return;
    int b = warp;
    int lo = 0, hi = NN;
    while (lo < hi) { int mid = (lo + hi) >> 1; if (batch[mid] < b) lo = mid + 1; else hi = mid; }
    int start = lo;
    hi = NN;
    while (lo < hi) { int mid = (lo + hi) >> 1; if (batch[mid] < b + 1) lo = mid + 1; else hi = mid; }
    int end = lo;
    float s = 0.f;
    for (int r = start; r < end; r++) s += G[(long)r * 32 + lane];
    ch[(long)b * 448 + lane] = __float2half(s);
}

// ---------------- BN/bias fold ----------------
__global__ void k_prep(const float* __restrict__ bias, const float* __restrict__ bn, int n,
                       float* __restrict__ sc, float* __restrict__ sh) {
    int j = blockIdx.x * blockDim.x + threadIdx.x;
    if (j >= n) return;
    float g = bn[j], be = bn[n + j], mu = bn[2 * n + j], va = bn[3 * n + j];
    float s = g * rsqrtf(va + 1e-5f);
    sc[j] = s;
    sh[j] = (bias[j] - mu) * s + be;
}

// ---------------- activation fp32 -> fp16 (hi only, x4 vectorized) ----------------
__global__ void k_ahalf(const float* __restrict__ in, __half* __restrict__ h, long n4) {
    long i = (long)blockIdx.x * blockDim.x + threadIdx.x;
    if (i >= n4) return;
    float4 v = *reinterpret_cast<const float4*>(in + i * 4);
    __half2* hp = reinterpret_cast<__half2*>(h + i * 4);
    hp[0] = __floats2half2_rn(v.x, v.y);
    hp[1] = __floats2half2_rn(v.z, v.w);
}

// weight [K][N] -> transposed fp16 hi(+lo) split, padded to [Np][Kp]; tl may be null
__global__ void k_whalf(const float* __restrict__ w, int K, int N, int Kp, int Np,
                        __half* __restrict__ th, __half* __restrict__ tl) {
    long i = (long)blockIdx.x * blockDim.x + threadIdx.x;
    if (i >= (long)Np * Kp) return;
    int n = (int)(i / Kp);
    int k = (int)(i % Kp);
    float v = (k < K && n < N) ? w[(long)k * N + n] : 0.f;
    __half hv = __float2half(v);
    th[i] = hv;
    if (tl) tl[i] = __float2half(v - __half2float(hv));
}

// ---------------- tensor-core GEMM (fp16; templated 1/2-MMA, cp.async 2-stage) ----------------
#define LDSM4(r0, r1, r2, r3, addr) \
    asm volatile("ldmatrix.sync.aligned.m8n8.x4.shared.b16 {%0,%1,%2,%3}, [%4];" \
                 : "=r"(r0), "=r"(r1), "=r"(r2), "=r"(r3) : "r"(addr))

#define MMA16816(c, a, b) \
    asm volatile("mma.sync.aligned.m16n8k16.row.col.f32.f16.f16.f32 " \
                 "{%0,%1,%2,%3}, {%4,%5,%6,%7}, {%8,%9}, {%0,%1,%2,%3};" \
                 : "+f"(c[0]), "+f"(c[1]), "+f"(c[2]), "+f"(c[3]) \
                 : "r"(a[0]), "r"(a[1]), "r"(a[2]), "r"(a[3]), "r"(b[0]), "r"(b[1]))

#define CPA16(d, s) asm volatile("cp.async.cg.shared.global [%0], [%1], 16;" :: "r"(d), "l"(s))
#define CP_COMMIT   asm volatile("cp.async.commit_group;")
#define CP_WAIT1    asm volatile("cp.async.wait_group 1;")
#define CP_WAIT0    asm volatile("cp.async.wait_group 0;")

// smem halves-stride 40 (80B rows): conflict-free 8-row ldmatrix.
#define SAW 40
#define SM_STG   20480
#define SM_BH    10240
#define SM_BL    15360
#define SM_TOTAL 40960

// C = relu((A @ (Bh[+Bl])^T) * sc + sh). A [16384 x Kp] fp16; B [Np x Kp] fp16.
template <bool USEL>
__global__ __launch_bounds__(256) void k_mma(
    const __half* __restrict__ Ah,
    const __half* __restrict__ Bh, const __half* __restrict__ Bl,
    int Kp,
    const float* __restrict__ sc, const float* __restrict__ sh,
    float* __restrict__ outF, __half* __restrict__ outH,
    int ldc, int cofs, int Nstore, int Nzero) {
    extern __shared__ __align__(128) __half dsm[];
    uint32_t sb = (uint32_t)__cvta_generic_to_shared(dsm);
    int tid = threadIdx.x;
    int lane = tid & 31, warp = tid >> 5;
    int wm = warp >> 1, wn = warp & 1;
    int bm = blockIdx.y * 128, bn = blockIdx.x * 64;

    float acc[2][4][4];
#pragma unroll
    for (int mi = 0; mi < 2; mi++)
#pragma unroll
        for (int ni = 0; ni < 4; ni++)
#pragma unroll
            for (int r = 0; r < 4; r++) acc[mi][ni][r] = 0.f;

    int ar = tid >> 2;           // 0..63
    int ac = (tid & 3) * 8;      // 0,8,16,24

    auto issue = [&](int kt, int stg) {
        long k0 = (long)kt * 32 + ac;
        uint32_t base = sb + stg * SM_STG;
#pragma unroll
        for (int rr = 0; rr < 2; rr++) {
            int row = ar + rr * 64;
            CPA16(base + ((row * SAW + ac) << 1), Ah + (long)(bm + row) * Kp + k0);
        }
        CPA16(base + SM_BH + ((ar * SAW + ac) << 1), Bh + (long)(bn + ar) * Kp + k0);
        if (USEL)
            CPA16(base + SM_BL + ((ar * SAW + ac) << 1), Bl + (long)(bn + ar) * Kp + k0);
    };

    int T = Kp >> 5;
    issue(0, 0);
    CP_COMMIT;
    int stg = 0;
    for (int kt = 0; kt < T; kt++) {
        if (kt + 1 < T) {
            issue(kt + 1, stg ^ 1);
            CP_COMMIT;
            CP_WAIT1;
        } else {
            CP_WAIT0;
        }
        __syncthreads();
        uint32_t base = sb + stg * SM_STG;
#pragma unroll
        for (int ks = 0; ks < 2; ks++) {
            uint32_t a_[2][4], bh_[4][2];
#pragma unroll
            for (int mi = 0; mi < 2; mi++) {
                int row = wm * 32 + mi * 16 + (lane & 15);
                int col = ks * 16 + (lane >> 4) * 8;
                uint32_t ad = base + ((row * SAW + col) << 1);
                LDSM4(a_[mi][0], a_[mi][1], a_[mi][2], a_[mi][3], ad);
            }
#pragma unroll
            for (int nh = 0; nh < 2; nh++) {
                int p = lane >> 3, l7 = lane & 7;
                int nrow = wn * 32 + nh * 16 + (p >> 1) * 8 + l7;
                int col = ks * 16 + (p & 1) * 8;
                uint32_t ad = base + SM_BH + ((nrow * SAW + col) << 1);
                LDSM4(bh_[2 * nh][0], bh_[2 * nh][1], bh_[2 * nh + 1][0], bh_[2 * nh + 1][1], ad);
            }
#pragma unroll
            for (int mi = 0; mi < 2; mi++)
#pragma unroll
                for (int ni = 0; ni < 4; ni++)
                    MMA16816(acc[mi][ni], a_[mi], bh_[ni]);
            if (USEL) {
                uint32_t bl_[4][2];
#pragma unroll
                for (int nh = 0; nh < 2; nh++) {
                    int p = lane >> 3, l7 = lane & 7;
                    int nrow = wn * 32 + nh * 16 + (p >> 1) * 8 + l7;
                    int col = ks * 16 + (p & 1) * 8;
                    uint32_t ad = base + SM_BL + ((nrow * SAW + col) << 1);
                    LDSM4(bl_[2 * nh][0], bl_[2 * nh][1], bl_[2 * nh + 1][0], bl_[2 * nh + 1][1], ad);
                }
#pragma unroll
                for (int mi = 0; mi < 2; mi++)
#pragma unroll
                    for (int ni = 0; ni < 4; ni++)
                        MMA16816(acc[mi][ni], a_[mi], bl_[ni]);
            }
        }
        __syncthreads();
        stg ^= 1;
    }

    // epilogue: scale/shift + relu; paired stores (gn even, pairs (r, r+1) share gm)
    int g = lane >> 2, t2 = (lane & 3) * 2;
#pragma unroll
    for (int mi = 0; mi < 2; mi++)
#pragma unroll
        for (int ni = 0; ni < 4; ni++)
#pragma unroll
            for (int rp = 0; rp < 2; rp++) {        // rp=0 -> r{0,1}; rp=1 -> r{2,3}
                int gm = bm + wm * 32 + mi * 16 + g + rp * 8;
                int gn = bn + wn * 32 + ni * 8 + t2;   // even; covers gn, gn+1
                if (gn < Nzero) {                       // Nzero even => pair-safe
                    float v0 = 0.f, v1 = 0.f;
                    if (gn < Nstore) {                  // Nstore even => pair-safe
                        v0 = acc[mi][ni][rp * 2 + 0] * sc[gn] + sh[gn];
                        v1 = acc[mi][ni][rp * 2 + 1] * sc[gn + 1] + sh[gn + 1];
                        v0 = (v0 > 0.f) ? v0 : 0.f;
                        v1 = (v1 > 0.f) ? v1 : 0.f;
                    }
                    long o = (long)gm * ldc + cofs + gn;   // even offset
                    if (outF) {
                        *reinterpret_cast<float2*>(outF + o) = make_float2(v0, v1);
                    } else {
                        *reinterpret_cast<__half2*>(outH + o) =
                            __floats2half2_rn(v0, v1);
                    }
                }
            }
}

// ---------------- final fc ----------------
__global__ void k_final(const float* __restrict__ Cc, const float* __restrict__ w,
                        const float* __restrict__ b, float* __restrict__ out) {
    int m = blockIdx.x * blockDim.x + threadIdx.x;
    if (m >= BB) return;
    float s = b[0];
#pragma unroll 4
    for (int j = 0; j < 100; j++) s = fmaf(Cc[(long)m * 100 + j], w[j], s);
    out[m] = s;
}

// ---------------- launch ----------------
extern "C" void kernel_launch(void* const* d_in, const int* in_sizes, int n_in,
                              void* d_out, int out_size) {
    const float* x      = (const float*)d_in[0];
    const int*   ei     = (const int*)d_in[1];
    const int*   batch  = (const int*)d_in[2];
    const float* fp     = (const float*)d_in[3];
    const float* tvf    = (const float*)d_in[4];
    const float* W1     = (const float*)d_in[5];
    const float* as1    = (const float*)d_in[6];
    const float* ad1    = (const float*)d_in[7];
    const float* b1     = (const float*)d_in[8];
    const float* W2     = (const float*)d_in[9];
    const float* as2    = (const float*)d_in[10];
    const float* ad2    = (const float*)d_in[11];
    const float* b2     = (const float*)d_in[12];
    const float* fc1_w  = (const float*)d_in[13];
    const float* fc1_b  = (const float*)d_in[14];
    const float* bn1    = (const float*)d_in[15];
    const float* fc2_w  = (const float*)d_in[16];
    const float* fc2_b  = (const float*)d_in[17];
    const float* bn2    = (const float*)d_in[18];
    const float* fc3_w  = (const float*)d_in[19];
    const float* fc3_b  = (const float*)d_in[20];
    const float* bn3    = (const float*)d_in[21];
    const float* fc4_w  = (const float*)d_in[22];
    const float* fc4_b  = (const float*)d_in[23];
    const float* bn4    = (const float*)d_in[24];
    const float* fcc1_w = (const float*)d_in[25];
    const float* fcc1_b = (const float*)d_in[26];
    const float* bnc    = (const float*)d_in[27];
    const float* fcc2_w = (const float*)d_in[28];
    const float* fcc2_b = (const float*)d_in[29];
    float* out = (float*)d_out;

    int E = in_sizes[1] / 2;

    static int inited = 0;
    static cudaStream_t sB = 0;
    static cudaEvent_t evF = 0, evJ = 0;
    if (!inited) {
        cudaFuncSetAttribute(k_mma<true>, cudaFuncAttributeMaxDynamicSharedMemorySize, SM_TOTAL);
        cudaFuncSetAttribute(k_mma<false>, cudaFuncAttributeMaxDynamicSharedMemorySize, SM_TOTAL);
        cudaStreamCreateWithFlags(&sB, cudaStreamNonBlocking);
        cudaEventCreateWithFlags(&evF, cudaEventDisableTiming);
        cudaEventCreateWithFlags(&evJ, cudaEventDisableTiming);
        inited = 1;
    }

    void *p_h, *p_g, *p_s, *p_t, *p_c1, *p_sc, *p_sh, *p_hf;
    cudaGetSymbolAddress(&p_h, d_hbuf);
    cudaGetSymbolAddress(&p_g, d_gbuf);
    cudaGetSymbolAddress(&p_s, d_sv);
    cudaGetSymbolAddress(&p_t, d_tvv);
    cudaGetSymbolAddress(&p_c1, d_c1);
    cudaGetSymbolAddress(&p_sc, d_scl);
    cudaGetSymbolAddress(&p_sh, d_shf);
    cudaGetSymbolAddress(&p_hf, g_hf);
    float* hbuf = (float*)p_h;  float* gbuf = (float*)p_g;
    float* sv = (float*)p_s;    float* tv = (float*)p_t;
    float* c1 = (float*)p_c1;
    float* scl = (float*)p_sc;  float* shf = (float*)p_sh;
    __half* hf = (__half*)p_hf;

    // fork: graph branch on sB, dense branch on stream 0
    cudaEventRecord(evF, 0);
    cudaStreamWaitEvent(sB, evF, 0);

    // ---- dense branch prologue (stream 0) ----
    {
        long n4 = 16384L * 1024 / 4;
        k_ahalf<<<(int)((n4 + 255) / 256), 256>>>(fp, hf + O_AFP, n4);
    }
    k_whalf<<<(448 * 1024 + 255) / 256, 256>>>(fc1_w, 1024, 400, 1024, 448, hf + O_W1_H, nullptr);
    k_prep<<<2, 256>>>(fc1_b, bn1, 400, scl + 0, shf + 0);
    {
        long n4 = 16384L * 256 / 4;
        k_ahalf<<<(int)((n4 + 255) / 256), 256>>>(tvf, hf + O_ATV, n4);
    }
    k_whalf<<<(448 * 256 + 255) / 256, 256>>>(fc3_w, 256, 400, 256, 448, hf + O_W3_H, nullptr);
    // fc1: [16384,1024]x[1024,400] -> fp1 [16384 x 448]  (1-MMA)
    k_mma<false><<<dim3(7, 128), 256, SM_TOTAL>>>(hf + O_AFP, hf + O_W1_H, nullptr,
                                                  1024, scl + 0, shf + 0,
                                                  nullptr, hf + O_FP1, 448, 0, 400, 448);

    // ---- graph branch (stream sB): CSR + GAT x2 + pool ----
    k_init_deg<<<(NN + 255) / 256, 256, 0, sB>>>();
    k_count<<<(E + 255) / 256, 256, 0, sB>>>(ei, E);
    k_blocksum<<<512, 1024, 0, sB>>>();
    k_scan_bsums<<<1, 512, 0, sB>>>();
    k_scan_final<<<512, 1024, 0, sB>>>();
    k_fill<<<(E + NN + 255) / 256, 256, 0, sB>>>(ei, E);
    k_node_linear<14, 14, 14, 16><<<(NN + 255) / 256, 256, 0, sB>>>(x, W1, as1, ad1, hbuf, sv, tv);
    k_gat_agg<14, 16, 16><<<(NN * 32 + 255) / 256, 256, 0, sB>>>(hbuf, sv, tv, b1, gbuf);
    k_node_linear<14, 16, 32, 32><<<(NN + 255) / 256, 256, 0, sB>>>(gbuf, W2, as2, ad2, hbuf, sv, tv);
    k_gat_agg<32, 32, 32><<<(NN * 32 + 255) / 256, 256, 0, sB>>>(hbuf, sv, tv, b2, gbuf);
    k_pool<<<(BB * 32 + 255) / 256, 256, 0, sB>>>(batch, gbuf, hf + O_CMB);

    // ---- dense branch continues (stream 0) ----
    k_prep<<<2, 256>>>(fc3_b, bn3, 400, scl + 600, shf + 600);
    // fc3: [16384,256]x[256,400] -> tv1  (1-MMA)
    k_mma<false><<<dim3(7, 128), 256, SM_TOTAL>>>(hf + O_ATV, hf + O_W3_H, nullptr,
                                                  256, scl + 600, shf + 600,
                                                  nullptr, hf + O_TV1, 448, 0, 400, 448);
    k_whalf<<<(256 * 448 + 255) / 256, 256>>>(fc2_w, 400, 200, 448, 256, hf + O_W2_H, hf + O_W2_L);
    k_prep<<<1, 256>>>(fc2_b, bn2, 200, scl + 400, shf + 400);
    // fc2: [16384,448]x[448,200] -> comb[:,32:232]  (2-MMA)
    k_mma<true><<<dim3(4, 128), 256, SM_TOTAL>>>(hf + O_FP1, hf + O_W2_H, hf + O_W2_L,
                                                 448, scl + 400, shf + 400,
                                                 nullptr, hf + O_CMB, 448, 32, 200, 200);
    k_whalf<<<(256 * 448 + 255) / 256, 256>>>(fc4_w, 400, 200, 448, 256, hf + O_W4_H, hf + O_W4_L);
    k_prep<<<1, 256>>>(fc4_b, bn4, 200, scl + 1000, shf + 1000);
    // fc4: [16384,448]x[448,200] -> comb[:,232:432], zero comb[:,432:448]  (2-MMA)
    k_mma<true><<<dim3(4, 128), 256, SM_TOTAL>>>(hf + O_TV1, hf + O_W4_H, hf + O_W4_L,
                                                 448, scl + 1000, shf + 1000,
                                                 nullptr, hf + O_CMB, 448, 232, 200, 216);
    k_whalf<<<(128 * 448 + 255) / 256, 256>>>(fcc1_w, 432, 100, 448, 128, hf + O_WC_H, hf + O_WC_L);
    k_prep<<<1, 128>>>(fcc1_b, bnc, 100, scl + 1200, shf + 1200);

    // join: fcc1 needs comb (pool on sB + fc2/fc4 on 0)
    cudaEventRecord(evJ, sB);
    cudaStreamWaitEvent(0, evJ, 0);

    // fcc1: [16384,448]x[448,100] -> c1 fp32  (2-MMA)
    k_mma<true><<<dim3(2, 128), 256, SM_TOTAL>>>(hf + O_CMB, hf + O_WC_H, hf + O_WC_L,
                                                 448, scl + 1200, shf + 1200,
                                                 c1, nullptr, 100, 0, 100, 100);
    k_final<<<(BB + 127) / 128, 128>>>(c1, fcc2_w, fcc2_b, out);
}